// round 1
// baseline (speedup 1.0000x reference)
#include <cuda_runtime.h>
#include <cstdint>

#define B_SZ 2048
#define T_SZ 256
#define IN_SZ 65
#define H_SZ 64
#define G_SZ 256           // 4*H
#define KK 129             // IN_SZ + H_SZ
#define BR 16              // batch rows per block
#define HXS 18             // padded row stride (in ull) for hx2 to spread banks
#define NTH 256

typedef unsigned long long ull;

__device__ __forceinline__ ull ffma2(ull a, ull b, ull c) {
    ull d;
    asm("fma.rn.f32x2 %0, %1, %2, %3;" : "=l"(d) : "l"(a), "l"(b), "l"(c));
    return d;
}
__device__ __forceinline__ ull fdup(float v) {
    ull d;
    asm("mov.b64 %0, {%1, %2};" : "=l"(d) : "f"(v), "f"(v));
    return d;
}
__device__ __forceinline__ void funpack(ull v, float& lo, float& hi) {
    asm("mov.b64 {%0, %1}, %2;" : "=f"(lo), "=f"(hi) : "l"(v));
}
__device__ __forceinline__ float ex2f(float x) {
    float y; asm("ex2.approx.f32 %0, %1;" : "=f"(y) : "f"(x)); return y;
}
__device__ __forceinline__ float rcpf(float x) {
    float y; asm("rcp.approx.f32 %0, %1;" : "=f"(y) : "f"(x)); return y;
}
// accurate-enough sigmoid/tanh: ex2.approx rel err ~2^-22, rcp ~1 ulp
__device__ __forceinline__ float sigf(float x) {
    return rcpf(1.0f + ex2f(-1.4426950408889634f * x));
}
__device__ __forceinline__ float tanhf_(float x) {
    return fmaf(2.0f, rcpf(1.0f + ex2f(-2.8853900817779268f * x)), -1.0f);
}

// smem layout sizes (bytes)
#define WS_BYTES (KK * G_SZ * 4)        // 132096  Ws[k][j] (k-major, transposed weights)
#define HX_BYTES (KK * HXS * 8)         // 18576   hx2[k][r] duplicated f32 pairs
#define GB_BYTES (BR * G_SZ * 4)        // 16384   gate buffer
#define BIAS_BYTES (G_SZ * 4)           // 1024
#define SMEM_TOTAL (WS_BYTES + HX_BYTES + GB_BYTES + BIAS_BYTES)  // 168080

__global__ __launch_bounds__(NTH, 1)
void lstm_fused_kernel(const float* __restrict__ x,
                       const float* __restrict__ Wih,
                       const float* __restrict__ Whh,
                       const float* __restrict__ bih,
                       const float* __restrict__ bhh,
                       const float* __restrict__ fcW,
                       const float* __restrict__ fcb,
                       float* __restrict__ out) {
    extern __shared__ char sm_raw[];
    float* Ws   = (float*)sm_raw;                           // [KK][G_SZ]
    ull*   hx2  = (ull*)(sm_raw + WS_BYTES);                // [KK][HXS] (only [..][0..15] used)
    float* gbuf = (float*)(sm_raw + WS_BYTES + HX_BYTES);   // [BR][G_SZ]
    float* bias = (float*)(sm_raw + WS_BYTES + HX_BYTES + GB_BYTES); // [G_SZ]

    const int tid = threadIdx.x;
    const int b0  = blockIdx.x * BR;

    // ---- one-time setup: transpose weights into Ws[k][j] ----
    for (int idx = tid; idx < G_SZ * IN_SZ; idx += NTH) {
        int j = idx / IN_SZ;
        int k = idx - j * IN_SZ;
        Ws[k * G_SZ + j] = Wih[idx];
    }
    for (int idx = tid; idx < G_SZ * H_SZ; idx += NTH) {
        int j = idx >> 6;
        int k = idx & 63;
        Ws[(IN_SZ + k) * G_SZ + j] = Whh[idx];
    }
    bias[tid] = bih[tid] + bhh[tid];
    // zero h-part of hx2
    for (int idx = tid; idx < H_SZ * BR; idx += NTH) {
        int k = IN_SZ + (idx >> 4);
        int r = idx & 15;
        hx2[k * HXS + r] = 0ULL;
    }
    // load x for t=0 (duplicated pairs)
    {
        int xr = tid >> 4;
        int l  = tid & 15;
        const float* xp = x + ((size_t)(b0 + xr) * T_SZ) * IN_SZ;
        #pragma unroll
        for (int m = 0; m < 5; ++m) {
            int i = l + m * 16;
            if (i < IN_SZ) hx2[i * HXS + xr] = fdup(xp[i]);
        }
    }
    __syncthreads();

    // ---- MAC-phase mapping: gates j0 = tx*4, rows r0 = ty*4 ----
    const int tx = tid >> 2;       // 0..63
    const int ty = tid & 3;        // 0..3
    // ---- update-phase mapping: row ur, units uu..uu+3 ----
    const int ur = tid >> 4;       // 0..15
    const int uu = (tid & 15) << 2; // 0..60

    const float4 bi4 = *(const float4*)(bias + uu);
    const float4 bf4 = *(const float4*)(bias + 64 + uu);
    const float4 bg4 = *(const float4*)(bias + 128 + uu);
    const float4 bo4 = *(const float4*)(bias + 192 + uu);
    float cst0 = 0.0f, cst1 = 0.0f, cst2 = 0.0f, cst3 = 0.0f;

    for (int t = 0; t < T_SZ; ++t) {
        // ===== MAC phase: gates[r][j] = sum_k Ws[k][j] * hx[r][k] =====
        ull a00 = 0, a01 = 0, a10 = 0, a11 = 0, a20 = 0, a21 = 0, a30 = 0, a31 = 0;
        const float* wsp = Ws + tx * 4;
        const ull*   hxp = hx2 + ty * 4;
        #pragma unroll 3
        for (int k = 0; k < KK; ++k) {
            ulonglong2 w   = *(const ulonglong2*)(wsp + (size_t)k * G_SZ);
            ulonglong2 h01 = *(const ulonglong2*)(hxp + (size_t)k * HXS);
            ulonglong2 h23 = *(const ulonglong2*)(hxp + (size_t)k * HXS + 2);
            a00 = ffma2(w.x, h01.x, a00); a01 = ffma2(w.y, h01.x, a01);
            a10 = ffma2(w.x, h01.y, a10); a11 = ffma2(w.y, h01.y, a11);
            a20 = ffma2(w.x, h23.x, a20); a21 = ffma2(w.y, h23.x, a21);
            a30 = ffma2(w.x, h23.y, a30); a31 = ffma2(w.y, h23.y, a31);
        }
        {
            float l0, h0, l1, h1;
            funpack(a00, l0, h0); funpack(a01, l1, h1);
            *(float4*)(gbuf + (ty * 4 + 0) * G_SZ + tx * 4) = make_float4(l0, h0, l1, h1);
            funpack(a10, l0, h0); funpack(a11, l1, h1);
            *(float4*)(gbuf + (ty * 4 + 1) * G_SZ + tx * 4) = make_float4(l0, h0, l1, h1);
            funpack(a20, l0, h0); funpack(a21, l1, h1);
            *(float4*)(gbuf + (ty * 4 + 2) * G_SZ + tx * 4) = make_float4(l0, h0, l1, h1);
            funpack(a30, l0, h0); funpack(a31, l1, h1);
            *(float4*)(gbuf + (ty * 4 + 3) * G_SZ + tx * 4) = make_float4(l0, h0, l1, h1);
        }
        __syncthreads();

        // ===== update phase =====
        // prefetch next timestep's x early (latency hidden under gate math)
        float xv0 = 0.f, xv1 = 0.f, xv2 = 0.f, xv3 = 0.f, xv4 = 0.f;
        const int l16 = tid & 15;
        const bool hasNext = (t + 1 < T_SZ);
        if (hasNext) {
            const float* xp = x + ((size_t)(b0 + ur) * T_SZ + (t + 1)) * IN_SZ;
            xv0 = xp[l16];
            xv1 = xp[l16 + 16];
            xv2 = xp[l16 + 32];
            xv3 = xp[l16 + 48];
            if (l16 == 0) xv4 = xp[64];
        }

        float4 gi4 = *(const float4*)(gbuf + ur * G_SZ + uu);
        float4 gf4 = *(const float4*)(gbuf + ur * G_SZ + 64 + uu);
        float4 gg4 = *(const float4*)(gbuf + ur * G_SZ + 128 + uu);
        float4 go4 = *(const float4*)(gbuf + ur * G_SZ + 192 + uu);

        {
            float iv = sigf(gi4.x + bi4.x);
            float fv = sigf(gf4.x + bf4.x);
            float gv = tanhf_(gg4.x + bg4.x);
            float ov = sigf(go4.x + bo4.x);
            cst0 = fv * cst0 + iv * gv;
            hx2[(IN_SZ + uu + 0) * HXS + ur] = fdup(ov * tanhf_(cst0));
        }
        {
            float iv = sigf(gi4.y + bi4.y);
            float fv = sigf(gf4.y + bf4.y);
            float gv = tanhf_(gg4.y + bg4.y);
            float ov = sigf(go4.y + bo4.y);
            cst1 = fv * cst1 + iv * gv;
            hx2[(IN_SZ + uu + 1) * HXS + ur] = fdup(ov * tanhf_(cst1));
        }
        {
            float iv = sigf(gi4.z + bi4.z);
            float fv = sigf(gf4.z + bf4.z);
            float gv = tanhf_(gg4.z + bg4.z);
            float ov = sigf(go4.z + bo4.z);
            cst2 = fv * cst2 + iv * gv;
            hx2[(IN_SZ + uu + 2) * HXS + ur] = fdup(ov * tanhf_(cst2));
        }
        {
            float iv = sigf(gi4.w + bi4.w);
            float fv = sigf(gf4.w + bf4.w);
            float gv = tanhf_(gg4.w + bg4.w);
            float ov = sigf(go4.w + bo4.w);
            cst3 = fv * cst3 + iv * gv;
            hx2[(IN_SZ + uu + 3) * HXS + ur] = fdup(ov * tanhf_(cst3));
        }

        if (hasNext) {
            hx2[(l16 +  0) * HXS + ur] = fdup(xv0);
            hx2[(l16 + 16) * HXS + ur] = fdup(xv1);
            hx2[(l16 + 32) * HXS + ur] = fdup(xv2);
            hx2[(l16 + 48) * HXS + ur] = fdup(xv3);
            if (l16 == 0) hx2[64 * HXS + ur] = fdup(xv4);
        }
        __syncthreads();
    }

    // ===== final FC head: out[b][o] = sigmoid(h . fcW[o] + fcb[o]) =====
    if (tid < BR * 7) {
        int r = tid / 7;
        int o = tid - r * 7;
        float s = fcb[o];
        const float* wrow = fcW + o * H_SZ;
        #pragma unroll 8
        for (int u = 0; u < H_SZ; ++u) {
            float lo, hi;
            funpack(hx2[(IN_SZ + u) * HXS + r], lo, hi);
            s += wrow[u] * lo;
        }
        out[(size_t)(b0 + r) * 7 + o] = sigf(s);
    }
}

extern "C" void kernel_launch(void* const* d_in, const int* in_sizes, int n_in,
                              void* d_out, int out_size) {
    const float* x    = (const float*)d_in[0];
    const float* Wih  = (const float*)d_in[1];
    const float* Whh  = (const float*)d_in[2];
    const float* bih  = (const float*)d_in[3];
    const float* bhh  = (const float*)d_in[4];
    const float* fcW  = (const float*)d_in[5];
    const float* fcb  = (const float*)d_in[6];
    float* out = (float*)d_out;

    cudaFuncSetAttribute(lstm_fused_kernel,
                         cudaFuncAttributeMaxDynamicSharedMemorySize, SMEM_TOTAL);
    lstm_fused_kernel<<<B_SZ / BR, NTH, SMEM_TOTAL>>>(x, Wih, Whh, bih, bhh, fcW, fcb, out);
}

// round 2
// speedup vs baseline: 1.1040x; 1.1040x over previous
#include <cuda_runtime.h>
#include <cstdint>

#define B_SZ 2048
#define T_SZ 256
#define IN_SZ 65
#define H_SZ 64
#define G_SZ 256           // 4*H
#define BR 16              // batch rows per block
#define HXS 18             // padded row stride (in ull) for dup-pair buffers
#define GBS 260            // padded gate-buffer row stride (floats)
#define NTH 512

typedef unsigned long long ull;

__device__ __forceinline__ ull ffma2(ull a, ull b, ull c) {
    ull d;
    asm("fma.rn.f32x2 %0, %1, %2, %3;" : "=l"(d) : "l"(a), "l"(b), "l"(c));
    return d;
}
__device__ __forceinline__ ull fdup(float v) {
    ull d;
    asm("mov.b64 %0, {%1, %2};" : "=l"(d) : "f"(v), "f"(v));
    return d;
}
__device__ __forceinline__ void funpack(ull v, float& lo, float& hi) {
    asm("mov.b64 {%0, %1}, %2;" : "=f"(lo), "=f"(hi) : "l"(v));
}
__device__ __forceinline__ float ex2f(float x) {
    float y; asm("ex2.approx.f32 %0, %1;" : "=f"(y) : "f"(x)); return y;
}
__device__ __forceinline__ float rcpf(float x) {
    float y; asm("rcp.approx.f32 %0, %1;" : "=f"(y) : "f"(x)); return y;
}
__device__ __forceinline__ float sigf(float x) {
    return rcpf(1.0f + ex2f(-1.4426950408889634f * x));
}
__device__ __forceinline__ float tanhf_(float x) {
    return fmaf(2.0f, rcpf(1.0f + ex2f(-2.8853900817779268f * x)), -1.0f);
}

// smem layout (bytes)
#define WS_BYTES   (129 * G_SZ * 4)        // 132096  Ws[k][j], k-major transposed weights
#define XB_BYTES   (IN_SZ * HXS * 8)       // 9360    xbuf dup pairs [65][HXS]
#define HB_BYTES   (H_SZ * HXS * 8)        // 9216    hbuf dup pairs [64][HXS]
#define GBA_BYTES  (BR * GBS * 4)          // 16640   partial gates, group A
#define GBB_BYTES  (BR * GBS * 4)          // 16640   partial gates, group B
#define SMEM_TOTAL (WS_BYTES + XB_BYTES + HB_BYTES + GBA_BYTES + GBB_BYTES)  // 183952

template<int N>
__device__ __forceinline__ void mac_loop(const float* __restrict__ wsp,
                                         const ull* __restrict__ hxp,
                                         ull* acc) {
#pragma unroll 4
    for (int k = 0; k < N; ++k) {
        ulonglong2 w   = *(const ulonglong2*)(wsp + (size_t)k * G_SZ);
        ulonglong2 h01 = *(const ulonglong2*)(hxp + (size_t)k * HXS);
        ulonglong2 h23 = *(const ulonglong2*)(hxp + (size_t)k * HXS + 2);
        acc[0] = ffma2(w.x, h01.x, acc[0]); acc[1] = ffma2(w.y, h01.x, acc[1]);
        acc[2] = ffma2(w.x, h01.y, acc[2]); acc[3] = ffma2(w.y, h01.y, acc[3]);
        acc[4] = ffma2(w.x, h23.x, acc[4]); acc[5] = ffma2(w.y, h23.x, acc[5]);
        acc[6] = ffma2(w.x, h23.y, acc[6]); acc[7] = ffma2(w.y, h23.y, acc[7]);
    }
}

__global__ __launch_bounds__(NTH, 1)
void lstm_fused_kernel(const float* __restrict__ x,
                       const float* __restrict__ Wih,
                       const float* __restrict__ Whh,
                       const float* __restrict__ bih,
                       const float* __restrict__ bhh,
                       const float* __restrict__ fcW,
                       const float* __restrict__ fcb,
                       float* __restrict__ out) {
    extern __shared__ char sm_raw[];
    float* Ws    = (float*)sm_raw;                                  // [129][256]
    ull*   xbuf  = (ull*)(sm_raw + WS_BYTES);                       // [65][HXS]
    ull*   hbuf  = (ull*)(sm_raw + WS_BYTES + XB_BYTES);            // [64][HXS]
    float* gbufA = (float*)(sm_raw + WS_BYTES + XB_BYTES + HB_BYTES);           // [16][GBS]
    float* gbufB = (float*)(sm_raw + WS_BYTES + XB_BYTES + HB_BYTES + GBA_BYTES); // [16][GBS]

    const int tid = threadIdx.x;
    const int b0  = blockIdx.x * BR;
    const bool isA = tid < 256;
    const int gi = tid & 255;
    const int tx = gi >> 2;        // gate group (0..63) -> gates tx*4..+3
    const int ty = gi & 3;         // row group  (0..3)  -> rows  ty*4..+3

    // ---- one-time setup ----
    // Ws[k][j] = Wih[j][k] for k<65 ; Ws[65+k][j] = Whh[j][k]
    for (int idx = tid; idx < G_SZ * IN_SZ; idx += NTH) {
        int j = idx / IN_SZ;
        int k = idx - j * IN_SZ;
        Ws[k * G_SZ + j] = Wih[idx];
    }
    for (int idx = tid; idx < G_SZ * H_SZ; idx += NTH) {
        int j = idx >> 6;
        int k = idx & 63;
        Ws[(IN_SZ + k) * G_SZ + j] = Whh[idx];
    }
    for (int idx = tid; idx < H_SZ * BR; idx += NTH) {
        hbuf[(idx >> 4) * HXS + (idx & 15)] = 0ULL;
    }
    // x for t=0
    const int xr  = tid >> 4;      // row 0..15 (group A only)
    const int l16 = tid & 15;
    if (isA) {
        const float* xp = x + ((size_t)(b0 + xr) * T_SZ) * IN_SZ;
#pragma unroll
        for (int m = 0; m < 5; ++m) {
            int i = l16 + m * 16;
            if (i < IN_SZ) xbuf[i * HXS + xr] = fdup(xp[i]);
        }
    }

    // ---- update-phase mapping: row ur, units uu, uu+1 ----
    const int ur = tid >> 5;           // 0..15
    const int uu = (tid & 31) << 1;    // 0..62
    const float bI0 = bih[uu]       + bhh[uu];
    const float bI1 = bih[uu + 1]   + bhh[uu + 1];
    const float bF0 = bih[64 + uu]  + bhh[64 + uu];
    const float bF1 = bih[65 + uu]  + bhh[65 + uu];
    const float bG0 = bih[128 + uu] + bhh[128 + uu];
    const float bG1 = bih[129 + uu] + bhh[129 + uu];
    const float bO0 = bih[192 + uu] + bhh[192 + uu];
    const float bO1 = bih[193 + uu] + bhh[193 + uu];
    float c0 = 0.0f, c1 = 0.0f;

    __syncthreads();

    for (int t = 0; t < T_SZ; ++t) {
        // ---- prefetch x[t+1] into registers (latency hidden under MAC) ----
        float xv0 = 0.f, xv1 = 0.f, xv2 = 0.f, xv3 = 0.f, xv4 = 0.f;
        const bool hasNext = (t + 1 < T_SZ);
        if (isA && hasNext) {
            const float* xp = x + ((size_t)(b0 + xr) * T_SZ + (t + 1)) * IN_SZ;
            xv0 = xp[l16];
            xv1 = xp[l16 + 16];
            xv2 = xp[l16 + 32];
            xv3 = xp[l16 + 48];
            if (l16 == 0) xv4 = xp[64];
        }

        // ---- MAC phase (split-k): group A does x-part, group B does h-part ----
        ull acc[8] = {0, 0, 0, 0, 0, 0, 0, 0};
        float* gb;
        if (isA) {
            mac_loop<IN_SZ>(Ws + tx * 4, xbuf + ty * 4, acc);
            gb = gbufA;
        } else {
            mac_loop<H_SZ>(Ws + IN_SZ * G_SZ + tx * 4, hbuf + ty * 4, acc);
            gb = gbufB;
        }
        {
            float l0, h0, l1, h1;
            funpack(acc[0], l0, h0); funpack(acc[1], l1, h1);
            *(float4*)(gb + (ty * 4 + 0) * GBS + tx * 4) = make_float4(l0, h0, l1, h1);
            funpack(acc[2], l0, h0); funpack(acc[3], l1, h1);
            *(float4*)(gb + (ty * 4 + 1) * GBS + tx * 4) = make_float4(l0, h0, l1, h1);
            funpack(acc[4], l0, h0); funpack(acc[5], l1, h1);
            *(float4*)(gb + (ty * 4 + 2) * GBS + tx * 4) = make_float4(l0, h0, l1, h1);
            funpack(acc[6], l0, h0); funpack(acc[7], l1, h1);
            *(float4*)(gb + (ty * 4 + 3) * GBS + tx * 4) = make_float4(l0, h0, l1, h1);
        }
        __syncthreads();

        // ---- update phase: 2 units per thread ----
        const float* ga = gbufA + ur * GBS + uu;
        const float* gbr = gbufB + ur * GBS + uu;
        float2 aI = *(const float2*)(ga);
        float2 pI = *(const float2*)(gbr);
        float2 aF = *(const float2*)(ga + 64);
        float2 pF = *(const float2*)(gbr + 64);
        float2 aG = *(const float2*)(ga + 128);
        float2 pG = *(const float2*)(gbr + 128);
        float2 aO = *(const float2*)(ga + 192);
        float2 pO = *(const float2*)(gbr + 192);

        {
            float iv = sigf(aI.x + pI.x + bI0);
            float fv = sigf(aF.x + pF.x + bF0);
            float gv = tanhf_(aG.x + pG.x + bG0);
            float ov = sigf(aO.x + pO.x + bO0);
            c0 = fv * c0 + iv * gv;
            hbuf[uu * HXS + ur] = fdup(ov * tanhf_(c0));
        }
        {
            float iv = sigf(aI.y + pI.y + bI1);
            float fv = sigf(aF.y + pF.y + bF1);
            float gv = tanhf_(aG.y + pG.y + bG1);
            float ov = sigf(aO.y + pO.y + bO1);
            c1 = fv * c1 + iv * gv;
            hbuf[(uu + 1) * HXS + ur] = fdup(ov * tanhf_(c1));
        }

        // ---- commit prefetched x[t+1] to shared ----
        if (isA && hasNext) {
            xbuf[(l16 +  0) * HXS + xr] = fdup(xv0);
            xbuf[(l16 + 16) * HXS + xr] = fdup(xv1);
            xbuf[(l16 + 32) * HXS + xr] = fdup(xv2);
            xbuf[(l16 + 48) * HXS + xr] = fdup(xv3);
            if (l16 == 0) xbuf[64 * HXS + xr] = fdup(xv4);
        }
        __syncthreads();
    }

    // ---- final FC head: out[b][o] = sigmoid(h . fcW[o] + fcb[o]) ----
    if (tid < BR * 7) {
        int r = tid / 7;
        int o = tid - r * 7;
        float s = fcb[o];
        const float* wrow = fcW + o * H_SZ;
#pragma unroll 8
        for (int u = 0; u < H_SZ; ++u) {
            float lo, hi;
            funpack(hbuf[u * HXS + r], lo, hi);
            s += wrow[u] * lo;
        }
        out[(size_t)(b0 + r) * 7 + o] = sigf(s);
    }
}

extern "C" void kernel_launch(void* const* d_in, const int* in_sizes, int n_in,
                              void* d_out, int out_size) {
    const float* x    = (const float*)d_in[0];
    const float* Wih  = (const float*)d_in[1];
    const float* Whh  = (const float*)d_in[2];
    const float* bih  = (const float*)d_in[3];
    const float* bhh  = (const float*)d_in[4];
    const float* fcW  = (const float*)d_in[5];
    const float* fcb  = (const float*)d_in[6];
    float* out = (float*)d_out;

    cudaFuncSetAttribute(lstm_fused_kernel,
                         cudaFuncAttributeMaxDynamicSharedMemorySize, SMEM_TOTAL);
    lstm_fused_kernel<<<B_SZ / BR, NTH, SMEM_TOTAL>>>(x, Wih, Whh, bih, bhh, fcW, fcb, out);
}

// round 3
// speedup vs baseline: 1.6702x; 1.5129x over previous
#include <cuda_runtime.h>
#include <cstdint>

#define B_SZ 2048
#define T_SZ 256
#define IN_SZ 65
#define H_SZ 64
#define G_SZ 256           // 4*H
#define BR 16              // batch rows per block
#define BRp 20             // padded row stride (floats) for x/h buffers
#define GBS 260            // padded gate-buffer row stride (floats)
#define NTH 512

typedef unsigned long long ull;

__device__ __forceinline__ ull ffma2(ull a, ull b, ull c) {
    ull d;
    asm("fma.rn.f32x2 %0, %1, %2, %3;" : "=l"(d) : "l"(a), "l"(b), "l"(c));
    return d;
}
__device__ __forceinline__ ull fdup(float v) {
    ull d;
    asm("mov.b64 %0, {%1, %2};" : "=l"(d) : "f"(v), "f"(v));
    return d;
}
__device__ __forceinline__ float ex2f(float x) {
    float y; asm("ex2.approx.f32 %0, %1;" : "=f"(y) : "f"(x)); return y;
}
__device__ __forceinline__ float rcpf(float x) {
    float y; asm("rcp.approx.f32 %0, %1;" : "=f"(y) : "f"(x)); return y;
}
__device__ __forceinline__ float sigf(float x) {
    return rcpf(1.0f + ex2f(-1.4426950408889634f * x));
}
__device__ __forceinline__ float tanhf_(float x) {
    return fmaf(2.0f, rcpf(1.0f + ex2f(-2.8853900817779268f * x)), -1.0f);
}

// smem layout (bytes)
#define WS_BYTES   (129 * G_SZ * 4)        // 132096  Ws[k][j], k-major transposed weights
#define XB_BYTES   (IN_SZ * BRp * 4)       // 5200    xbuf [65][BRp] plain floats
#define HB_BYTES   (H_SZ * BRp * 4)        // 5120    hbuf [64][BRp] plain floats
#define GBA_BYTES  (BR * GBS * 4)          // 16640   partial gates, group A
#define GBB_BYTES  (BR * GBS * 4)          // 16640   partial gates, group B
#define SMEM_TOTAL (WS_BYTES + XB_BYTES + HB_BYTES + GBA_BYTES + GBB_BYTES)  // 175696

template<int N>
__device__ __forceinline__ void mac_loop(const float* __restrict__ wp,
                                         const float* __restrict__ hp,
                                         ull* acc) {
#pragma unroll 4
    for (int k = 0; k < N; ++k) {
        ulonglong2 w = *(const ulonglong2*)(wp);   // 4 gates = 2 packed pairs
        float4 h = *(const float4*)(hp);           // 4 rows, plain floats
        wp += G_SZ;
        hp += BRp;
        ull h0 = fdup(h.x), h1 = fdup(h.y), h2 = fdup(h.z), h3 = fdup(h.w);
        acc[0] = ffma2(w.x, h0, acc[0]); acc[1] = ffma2(w.y, h0, acc[1]);
        acc[2] = ffma2(w.x, h1, acc[2]); acc[3] = ffma2(w.y, h1, acc[3]);
        acc[4] = ffma2(w.x, h2, acc[4]); acc[5] = ffma2(w.y, h2, acc[5]);
        acc[6] = ffma2(w.x, h3, acc[6]); acc[7] = ffma2(w.y, h3, acc[7]);
    }
}

__global__ __launch_bounds__(NTH, 1)
void lstm_fused_kernel(const float* __restrict__ x,
                       const float* __restrict__ Wih,
                       const float* __restrict__ Whh,
                       const float* __restrict__ bih,
                       const float* __restrict__ bhh,
                       const float* __restrict__ fcW,
                       const float* __restrict__ fcb,
                       float* __restrict__ out) {
    extern __shared__ char sm_raw[];
    float* Ws    = (float*)sm_raw;                                   // [129][256]
    float* xbuf  = (float*)(sm_raw + WS_BYTES);                      // [65][BRp]
    float* hbuf  = (float*)(sm_raw + WS_BYTES + XB_BYTES);           // [64][BRp]
    float* gbufA = (float*)(sm_raw + WS_BYTES + XB_BYTES + HB_BYTES);             // [16][GBS]
    float* gbufB = (float*)(sm_raw + WS_BYTES + XB_BYTES + HB_BYTES + GBA_BYTES); // [16][GBS]

    const int tid = threadIdx.x;
    const int b0  = blockIdx.x * BR;
    const bool isA = tid < 256;
    const int gi = tid & 255;
    const int tx = gi >> 2;        // gate quad (0..63) -> gates tx*4..+3
    const int ty = gi & 3;         // row quad  (0..3)  -> rows  ty*4..+3

    // ---- one-time setup: Ws[k][j] = W[j][k] transposed, k-major ----
    for (int idx = tid; idx < G_SZ * IN_SZ; idx += NTH) {
        int j = idx / IN_SZ;
        int k = idx - j * IN_SZ;
        Ws[k * G_SZ + j] = Wih[idx];
    }
    for (int idx = tid; idx < G_SZ * H_SZ; idx += NTH) {
        int j = idx >> 6;
        int k = idx & 63;
        Ws[(IN_SZ + k) * G_SZ + j] = Whh[idx];
    }
    for (int idx = tid; idx < H_SZ * BRp; idx += NTH) {
        hbuf[idx] = 0.0f;
    }
    // x for t=0
    const int xr  = tid >> 4;      // row 0..15 (group A only)
    const int l16 = tid & 15;
    if (isA) {
        const float* xp = x + ((size_t)(b0 + xr) * T_SZ) * IN_SZ;
#pragma unroll
        for (int m = 0; m < 5; ++m) {
            int i = l16 + m * 16;
            if (i < IN_SZ) xbuf[i * BRp + xr] = xp[i];
        }
    }

    // ---- update-phase mapping: row ur, units uu, uu+1 ----
    const int ur = tid >> 5;           // 0..15
    const int uu = (tid & 31) << 1;    // 0..62
    const float bI0 = bih[uu]       + bhh[uu];
    const float bI1 = bih[uu + 1]   + bhh[uu + 1];
    const float bF0 = bih[64 + uu]  + bhh[64 + uu];
    const float bF1 = bih[65 + uu]  + bhh[65 + uu];
    const float bG0 = bih[128 + uu] + bhh[128 + uu];
    const float bG1 = bih[129 + uu] + bhh[129 + uu];
    const float bO0 = bih[192 + uu] + bhh[192 + uu];
    const float bO1 = bih[193 + uu] + bhh[193 + uu];
    float c0 = 0.0f, c1 = 0.0f;

    __syncthreads();

    for (int t = 0; t < T_SZ; ++t) {
        // ---- prefetch x[t+1] into registers (latency hidden under MAC) ----
        float xv0 = 0.f, xv1 = 0.f, xv2 = 0.f, xv3 = 0.f, xv4 = 0.f;
        const bool hasNext = (t + 1 < T_SZ);
        if (isA && hasNext) {
            const float* xp = x + ((size_t)(b0 + xr) * T_SZ + (t + 1)) * IN_SZ;
            xv0 = xp[l16];
            xv1 = xp[l16 + 16];
            xv2 = xp[l16 + 32];
            xv3 = xp[l16 + 48];
            if (l16 == 0) xv4 = xp[64];
        }

        // ---- MAC phase (split-k): group A does x-part, group B does h-part ----
        ull acc[8] = {0, 0, 0, 0, 0, 0, 0, 0};
        float* gb;
        if (isA) {
            mac_loop<IN_SZ>(Ws + tx * 4, xbuf + ty * 4, acc);
            gb = gbufA;
        } else {
            mac_loop<H_SZ>(Ws + IN_SZ * G_SZ + tx * 4, hbuf + ty * 4, acc);
            gb = gbufB;
        }
        // store packed gate-pairs: row ty*4+i, gates tx*4..+3
#pragma unroll
        for (int i = 0; i < 4; ++i) {
            *(ulonglong2*)(gb + (ty * 4 + i) * GBS + tx * 4) =
                make_ulonglong2(acc[2 * i], acc[2 * i + 1]);
        }
        __syncthreads();

        // ---- update phase: 2 units per thread ----
        const float* ga  = gbufA + ur * GBS + uu;
        const float* gbr = gbufB + ur * GBS + uu;
        float2 aI = *(const float2*)(ga);
        float2 pI = *(const float2*)(gbr);
        float2 aF = *(const float2*)(ga + 64);
        float2 pF = *(const float2*)(gbr + 64);
        float2 aG = *(const float2*)(ga + 128);
        float2 pG = *(const float2*)(gbr + 128);
        float2 aO = *(const float2*)(ga + 192);
        float2 pO = *(const float2*)(gbr + 192);

        {
            float iv = sigf(aI.x + pI.x + bI0);
            float fv = sigf(aF.x + pF.x + bF0);
            float gv = tanhf_(aG.x + pG.x + bG0);
            float ov = sigf(aO.x + pO.x + bO0);
            c0 = fv * c0 + iv * gv;
            hbuf[uu * BRp + ur] = ov * tanhf_(c0);
        }
        {
            float iv = sigf(aI.y + pI.y + bI1);
            float fv = sigf(aF.y + pF.y + bF1);
            float gv = tanhf_(aG.y + pG.y + bG1);
            float ov = sigf(aO.y + pO.y + bO1);
            c1 = fv * c1 + iv * gv;
            hbuf[(uu + 1) * BRp + ur] = ov * tanhf_(c1);
        }

        // ---- commit prefetched x[t+1] to shared ----
        if (isA && hasNext) {
            xbuf[(l16 +  0) * BRp + xr] = xv0;
            xbuf[(l16 + 16) * BRp + xr] = xv1;
            xbuf[(l16 + 32) * BRp + xr] = xv2;
            xbuf[(l16 + 48) * BRp + xr] = xv3;
            if (l16 == 0) xbuf[64 * BRp + xr] = xv4;
        }
        __syncthreads();
    }

    // ---- final FC head: out[b][o] = sigmoid(h . fcW[o] + fcb[o]) ----
    if (tid < BR * 7) {
        int r = tid / 7;
        int o = tid - r * 7;
        float s = fcb[o];
        const float* wrow = fcW + o * H_SZ;
#pragma unroll 8
        for (int u = 0; u < H_SZ; ++u) {
            s += wrow[u] * hbuf[u * BRp + r];
        }
        out[(size_t)(b0 + r) * 7 + o] = sigf(s);
    }
}

extern "C" void kernel_launch(void* const* d_in, const int* in_sizes, int n_in,
                              void* d_out, int out_size) {
    const float* x    = (const float*)d_in[0];
    const float* Wih  = (const float*)d_in[1];
    const float* Whh  = (const float*)d_in[2];
    const float* bih  = (const float*)d_in[3];
    const float* bhh  = (const float*)d_in[4];
    const float* fcW  = (const float*)d_in[5];
    const float* fcb  = (const float*)d_in[6];
    float* out = (float*)d_out;

    cudaFuncSetAttribute(lstm_fused_kernel,
                         cudaFuncAttributeMaxDynamicSharedMemorySize, SMEM_TOTAL);
    lstm_fused_kernel<<<B_SZ / BR, NTH, SMEM_TOTAL>>>(x, Wih, Whh, bih, bhh, fcW, fcb, out);
}